// round 5
// baseline (speedup 1.0000x reference)
#include <cuda_runtime.h>
#include <cuda_bf16.h>

#define BATCH 8
#define NBOX 2048
#define MAXDET 100
#define THREADS 128
#define MIN_SIZE 25.0f
#define SCORE_THR 0.001f
#define CIOU 0.23076923f      // 0.3/1.3 : iou>0.3 <=> inter > CIOU*(areaA+areaB)

typedef unsigned long long u64;

// pack (score, idx): larger packed == (higher score, then smaller idx)
__device__ __forceinline__ u64 pack_si(float s, int idx) {
    return ((u64)__float_as_uint(s) << 32) | (unsigned)(~idx);
}

// (m1,m2) desc, (o1,o2) desc -> (m1,m2) = exact top2 of union
__device__ __forceinline__ void merge_top2(u64& m1, u64& m2, u64 o1, u64 o2) {
    bool g = m1 > o1;
    u64 hi  = g ? m1 : o1;
    u64 mid = g ? (m2 > o1 ? m2 : o1) : (o2 > m1 ? o2 : m1);
    m1 = hi; m2 = mid;
}

extern __shared__ char smem_raw[];
// layout (16B aligned blocks):
//   sbox  : float4[NBOX]   (broadcast table, never compacted)
//   boxA  : float4[NBOX]   pkA : u64[NBOX]
//   boxB  : float4[NBOX]   pkB : u64[NBOX]
//   ws    : u64[8]         wcnt: int[4]
#define SMEM_BYTES (3 * NBOX * 16 + 2 * NBOX * 8 + 8 * 8 + 4 * 4)

__global__ __launch_bounds__(THREADS, 1)
void nms_kernel(const float* __restrict__ boxes,
                const float* __restrict__ scores,
                float* __restrict__ out,
                int write_mask)
{
    float4* sbox = (float4*)smem_raw;
    float4* boxA = sbox + NBOX;
    u64*    pkA  = (u64*)(boxA + NBOX);
    float4* boxB = (float4*)(pkA + NBOX);
    u64*    pkB  = (u64*)(boxB + NBOX);
    u64*    ws   = (u64*)(pkB + NBOX);
    int*    wcnt = (int*)(ws + 8);

    const int img  = blockIdx.x;
    const int tid  = threadIdx.x;
    const int warp = tid >> 5;
    const int lane = tid & 31;

    // ---- fill: validity filter; invalid -> pk = 0 ----
    const float4* bp = (const float4*)(boxes + (size_t)img * NBOX * 4);
    const float*  sp = scores + (size_t)img * NBOX;
    #pragma unroll
    for (int p = 0; p < NBOX / THREADS; p++) {
        int i = p * THREADS + tid;
        float4 b = bp[i];
        float  s = sp[i];
        float w = b.z - b.x;
        float h = b.w - b.y;
        bool valid = (w >= MIN_SIZE) && (h >= MIN_SIZE) && (s >= SCORE_THR);
        sbox[i] = b;
        boxA[i] = b;
        pkA[i]  = valid ? pack_si(s, i) : 0ULL;
    }

    // ---- init output padding: [img,0,0,0,0] rows, mask = 0 ----
    float* outr = out + (size_t)img * MAXDET * 5;
    float* outm = out + (size_t)BATCH * MAXDET * 5 + (size_t)img * MAXDET;
    #pragma unroll
    for (int i = tid; i < MAXDET; i += THREADS) {
        outr[i * 5 + 0] = (float)img;
        outr[i * 5 + 1] = 0.f;
        outr[i * 5 + 2] = 0.f;
        outr[i * 5 + 3] = 0.f;
        outr[i * 5 + 4] = 0.f;
        if (write_mask) outm[i] = 0.f;
    }
    __syncthreads();

    int nlive = NBOX;
    int k = 0, par = 0;
    float4 cb1 = make_float4(0.f, 0.f, 0.f, 0.f);   // dummy: suppresses nothing
    float4 cb2 = cb1;
    float  ca1 = 0.f, ca2 = 0.f;

    while (k < MAXDET) {
        float4* rbox = par ? boxB : boxA;  u64* rpk = par ? pkB : pkA;
        float4* wbox = par ? boxA : boxB;  u64* wpk = par ? pkA : pkB;

        // ---- phase A: suppress vs (cb1, cb2), keep-flags, top-2 of survivors ----
        u64 m1 = 0ULL, m2 = 0ULL;
        unsigned flags = 0;
        int cnt = 0;
        for (int i = tid, j = 0; i < nlive; i += THREADS, j++) {
            u64 pk = rpk[i];
            float4 b = rbox[i];
            float cab = CIOU * ((b.z - b.x) * (b.w - b.y));
            float ix1 = fminf(cb1.z, b.z) - fmaxf(cb1.x, b.x);
            float iy1 = fminf(cb1.w, b.w) - fmaxf(cb1.y, b.y);
            float in1 = fmaxf(ix1, 0.f) * fmaxf(iy1, 0.f);
            float ix2 = fminf(cb2.z, b.z) - fmaxf(cb2.x, b.x);
            float iy2 = fminf(cb2.w, b.w) - fmaxf(cb2.y, b.y);
            float in2 = fmaxf(ix2, 0.f) * fmaxf(iy2, 0.f);
            bool dead = (in1 > ca1 + cab) || (in2 > ca2 + cab);
            bool keep = (pk != 0ULL) && !dead;
            if (keep) {
                flags |= 1u << j;
                cnt++;
                if (pk > m1) { m2 = m1; m1 = pk; }
                else if (pk > m2) { m2 = pk; }
            }
        }

        // warp top-2 + warp survivor count + intra-warp exclusive prefix
        #pragma unroll
        for (int off = 16; off > 0; off >>= 1) {
            u64 o1 = __shfl_xor_sync(0xffffffffu, m1, off);
            u64 o2 = __shfl_xor_sync(0xffffffffu, m2, off);
            merge_top2(m1, m2, o1, o2);
        }
        int wtot = __reduce_add_sync(0xffffffffu, cnt);
        int pre = cnt;
        #pragma unroll
        for (int off = 1; off < 32; off <<= 1) {
            int o = __shfl_up_sync(0xffffffffu, pre, off);
            if (lane >= off) pre += o;
        }
        pre -= cnt;                                   // exclusive prefix
        if (lane == 0) { ws[2 * warp] = m1; ws[2 * warp + 1] = m2; wcnt[warp] = wtot; }
        __syncthreads();

        // ---- global top-2, write bases, new live count (all threads, redundant) ----
        u64 g1 = 0ULL, g2 = 0ULL;
        #pragma unroll
        for (int j = 0; j < 4; j++) merge_top2(g1, g2, ws[2 * j], ws[2 * j + 1]);
        int base = pre, nnew = 0;
        #pragma unroll
        for (int w = 0; w < 4; w++) { int c = wcnt[w]; if (w < warp) base += c; nnew += c; }

        if (g1 == 0ULL) break;                        // nothing live (uniform)

        int c1 = (int)~(unsigned)(g1 & 0xffffffffu);
        int c2 = (g2 != 0ULL) ? (int)~(unsigned)(g2 & 0xffffffffu) : c1;
        float4 nb1 = sbox[c1];
        float4 nb2 = sbox[c2];

        // accept t2 iff it exists and IoU(t1,t2) <= 0.3
        float na1 = CIOU * ((nb1.z - nb1.x) * (nb1.w - nb1.y));
        float na2 = CIOU * ((nb2.z - nb2.x) * (nb2.w - nb2.y));
        float ox = fminf(nb1.z, nb2.z) - fmaxf(nb1.x, nb2.x);
        float oy = fminf(nb1.w, nb2.w) - fmaxf(nb1.y, nb2.y);
        float ov = fmaxf(ox, 0.f) * fmaxf(oy, 0.f);
        bool sel2 = (g2 != 0ULL) && !(ov > na1 + na2);
        if (!sel2) { nb2 = nb1; na2 = na1; }          // double-suppress: idempotent

        if (tid == 0) {
            outr[k * 5 + 1] = nb1.x;
            outr[k * 5 + 2] = nb1.y;
            outr[k * 5 + 3] = nb1.z;
            outr[k * 5 + 4] = nb1.w;
            if (write_mask) outm[k] = 1.f;
            if (sel2 && k + 1 < MAXDET) {
                outr[(k + 1) * 5 + 1] = nb2.x;
                outr[(k + 1) * 5 + 2] = nb2.y;
                outr[(k + 1) * 5 + 3] = nb2.z;
                outr[(k + 1) * 5 + 4] = nb2.w;
                if (write_mask) outm[k + 1] = 1.f;
            }
        }

        // ---- phase B: compact survivors into the alternate buffer ----
        unsigned f = flags;
        while (f) {
            int j = __ffs(f) - 1; f &= f - 1;
            int src = tid + j * THREADS;
            wpk[base]  = rpk[src];
            wbox[base] = rbox[src];
            base++;
        }
        __syncthreads();

        nlive = nnew;
        par ^= 1;
        cb1 = nb1; cb2 = nb2; ca1 = na1; ca2 = na2;
        k += sel2 ? 2 : 1;
    }
}

extern "C" void kernel_launch(void* const* d_in, const int* in_sizes, int n_in,
                              void* d_out, int out_size) {
    const float* boxes  = (const float*)d_in[0];   // [8,2048,4] f32
    const float* scores = (const float*)d_in[1];   // [8,2048]   f32
    float* out = (float*)d_out;
    int write_mask = (out_size >= BATCH * MAXDET * 5 + BATCH * MAXDET) ? 1 : 0;

    static int attr_done = 0;
    if (!attr_done) {
        cudaFuncSetAttribute(nms_kernel,
                             cudaFuncAttributeMaxDynamicSharedMemorySize,
                             SMEM_BYTES);
        attr_done = 1;
    }
    nms_kernel<<<BATCH, THREADS, SMEM_BYTES>>>(boxes, scores, out, write_mask);
}

// round 6
// speedup vs baseline: 1.7090x; 1.7090x over previous
#include <cuda_runtime.h>
#include <cuda_bf16.h>

#define BATCH 8
#define NBOX 2048
#define MAXDET 100
#define THREADS 128
#define EPT 16                      // elements per thread (blocked)
#define MIN_SIZE 25.0f
#define SCORE_THR 0.001f
#define CIOU 0.23076923f            // 0.3/1.3 : iou>0.3 <=> inter > CIOU*(A+B)
#define RINF 0x7FFFFFFF
#define FULL 0xFFFFFFFFu

typedef unsigned long long u64;
typedef unsigned int u32;

// key: (score bits << 32) | ~idx  -> descending sort == (score desc, idx asc)
__device__ __forceinline__ u64 pack_si(float s, int idx) {
    return ((u64)__float_as_uint(s) << 32) | (u32)(~idx);
}

extern __shared__ char smem_raw[];
// sboxO: float4[NBOX] (orig order) | ssort: float4[NBOX] (rank order)
// skey:  u64[NBOX] | wr: int[2][8]
#define SMEM_BYTES (NBOX * 16 * 2 + NBOX * 8 + 2 * 8 * 4 + 16)

__global__ __launch_bounds__(THREADS, 1)
void nms_kernel(const float* __restrict__ boxes,
                const float* __restrict__ scores,
                float* __restrict__ out,
                int write_mask)
{
    float4* sboxO = (float4*)smem_raw;
    float4* ssort = sboxO + NBOX;
    u64*    skey  = (u64*)(ssort + NBOX);
    int*    wr    = (int*)(skey + NBOX);

    const int img  = blockIdx.x;
    const int tid  = threadIdx.x;
    const int warp = tid >> 5;
    const int lane = tid & 31;
    const int base = tid * EPT;     // blocked rank ownership

    // ---- load, validity filter, build keys (invalid -> 0) ----
    const float4* bp = (const float4*)(boxes + (size_t)img * NBOX * 4);
    const float*  sp = scores + (size_t)img * NBOX;
    #pragma unroll
    for (int p = 0; p < NBOX / THREADS; p++) {
        int i = p * THREADS + tid;
        float4 b = bp[i];
        float  s = sp[i];
        float w = b.z - b.x;
        float h = b.w - b.y;
        bool valid = (w >= MIN_SIZE) && (h >= MIN_SIZE) && (s >= SCORE_THR);
        sboxO[i] = b;
        skey[i]  = valid ? pack_si(s, i) : 0ULL;
    }

    // ---- init output padding ----
    float* outr = out + (size_t)img * MAXDET * 5;
    float* outm = out + (size_t)BATCH * MAXDET * 5 + (size_t)img * MAXDET;
    #pragma unroll
    for (int i = tid; i < MAXDET; i += THREADS) {
        outr[i * 5 + 0] = (float)img;
        outr[i * 5 + 1] = 0.f;
        outr[i * 5 + 2] = 0.f;
        outr[i * 5 + 3] = 0.f;
        outr[i * 5 + 4] = 0.f;
        if (write_mask) outm[i] = 0.f;
    }
    __syncthreads();

    // ================= bitonic sort (descending), blocked-register hybrid ====
    u64 key[EPT];
    #pragma unroll
    for (int e = 0; e < EPT; e++) key[e] = skey[base + e];

    // presort k=2..16 entirely in registers
    #pragma unroll
    for (int k = 2; k <= 16; k <<= 1) {
        #pragma unroll
        for (int j = k >> 1; j > 0; j >>= 1) {
            #pragma unroll
            for (int e = 0; e < EPT; e++) {
                if ((e & j) == 0) {
                    int f = e | j;
                    bool up = (((base + e) & k) == 0);   // descending region
                    u64 x = key[e], y = key[f];
                    bool sw = up ? (x < y) : (x > y);
                    if (sw) { key[e] = y; key[f] = x; }
                }
            }
        }
    }

    // k-phases 32..2048: shared stages for j>=16, register tail j<=8
    #pragma unroll 1
    for (int kk = 32; kk <= NBOX; kk <<= 1) {
        #pragma unroll
        for (int e = 0; e < EPT; e++) skey[base + e] = key[e];
        __syncthreads();
        #pragma unroll 1
        for (int j = kk >> 1; j >= 16; j >>= 1) {
            #pragma unroll
            for (int n = 0; n < NBOX / 2 / THREADS; n++) {
                int idx = tid + n * THREADS;
                int i1 = ((idx & ~(j - 1)) << 1) | (idx & (j - 1));
                int i2 = i1 | j;
                bool up = ((i1 & kk) == 0);
                u64 x = skey[i1], y = skey[i2];
                bool sw = up ? (x < y) : (x > y);
                if (sw) { skey[i1] = y; skey[i2] = x; }
            }
            __syncthreads();
        }
        #pragma unroll
        for (int e = 0; e < EPT; e++) key[e] = skey[base + e];
        {
            bool up = ((base & kk) == 0);               // constant per thread
            #pragma unroll
            for (int j = 8; j > 0; j >>= 1) {
                #pragma unroll
                for (int e = 0; e < EPT; e++) {
                    if ((e & j) == 0) {
                        int f = e | j;
                        u64 x = key[e], y = key[f];
                        bool sw = up ? (x < y) : (x > y);
                        if (sw) { key[e] = y; key[f] = x; }
                    }
                }
            }
        }
    }

    // ---- gather sorted boxes into regs + broadcast table; init live mask ----
    float4 mybox[EPT];
    float  myca[EPT];
    u32 live = 0;
    #pragma unroll
    for (int e = 0; e < EPT; e++) {
        int idx = (int)(~(u32)(key[e] & 0xffffffffu)) & (NBOX - 1);
        float4 b = sboxO[idx];
        mybox[e] = b;
        myca[e]  = CIOU * ((b.z - b.x) * (b.w - b.y));
        ssort[base + e] = b;
        if (key[e] != 0ULL) live |= 1u << e;
    }
    __syncthreads();

    // ================= dual-selection greedy rounds ==========================
    int k = 0, par = 0;
    while (k < MAXDET) {
        // first & second live ranks (local -> warp REDUX.MIN -> cross-warp)
        int a = live ? (base + __ffs(live) - 1) : RINF;
        u32 rest = live & (live - 1);
        int b2 = rest ? (base + __ffs(rest) - 1) : RINF;
        int w1 = __reduce_min_sync(FULL, a);
        int cnd = (a == w1) ? b2 : a;
        int w2 = __reduce_min_sync(FULL, cnd);
        if (lane == 0) { wr[par * 8 + 2 * warp] = w1; wr[par * 8 + 2 * warp + 1] = w2; }
        __syncthreads();

        int r1 = RINF, r2 = RINF;
        #pragma unroll
        for (int w = 0; w < 4; w++) {
            int x = wr[par * 8 + 2 * w], y = wr[par * 8 + 2 * w + 1];   // x <= y
            if (x < r1) { r2 = min(r1, y); r1 = x; }
            else        { r2 = min(r2, x); }
        }
        par ^= 1;

        if (r1 == RINF) break;                       // nothing live (uniform)

        float4 cb1 = ssort[r1];
        bool has2 = (r2 != RINF);
        float4 cb2 = has2 ? ssort[r2] : cb1;

        float ca1 = CIOU * ((cb1.z - cb1.x) * (cb1.w - cb1.y));
        float ca2 = CIOU * ((cb2.z - cb2.x) * (cb2.w - cb2.y));
        float ox = fminf(cb1.z, cb2.z) - fmaxf(cb1.x, cb2.x);
        float oy = fminf(cb1.w, cb2.w) - fmaxf(cb1.y, cb2.y);
        float ov = fmaxf(ox, 0.f) * fmaxf(oy, 0.f);
        bool sel2 = has2 && !(ov > ca1 + ca2);
        if (!sel2) { cb2 = cb1; ca2 = ca1; }         // double-suppress: idempotent

        if (tid == 0) {
            outr[k * 5 + 1] = cb1.x;
            outr[k * 5 + 2] = cb1.y;
            outr[k * 5 + 3] = cb1.z;
            outr[k * 5 + 4] = cb1.w;
            if (write_mask) outm[k] = 1.f;
            if (sel2 && k + 1 < MAXDET) {
                outr[(k + 1) * 5 + 1] = cb2.x;
                outr[(k + 1) * 5 + 2] = cb2.y;
                outr[(k + 1) * 5 + 3] = cb2.z;
                outr[(k + 1) * 5 + 4] = cb2.w;
                if (write_mask) outm[k + 1] = 1.f;
            }
        }

        // fused dual suppression on register-resident boxes (kills r1/r2 too)
        #pragma unroll
        for (int e = 0; e < EPT; e++) {
            float4 b = mybox[e];
            float ix1 = fminf(cb1.z, b.z) - fmaxf(cb1.x, b.x);
            float iy1 = fminf(cb1.w, b.w) - fmaxf(cb1.y, b.y);
            float in1 = fmaxf(ix1, 0.f) * fmaxf(iy1, 0.f);
            float ix2 = fminf(cb2.z, b.z) - fmaxf(cb2.x, b.x);
            float iy2 = fminf(cb2.w, b.w) - fmaxf(cb2.y, b.y);
            float in2 = fmaxf(ix2, 0.f) * fmaxf(iy2, 0.f);
            bool dead = (in1 > ca1 + myca[e]) || (in2 > ca2 + myca[e]);
            if (dead) live &= ~(1u << e);
        }

        k += sel2 ? 2 : 1;
    }
}

extern "C" void kernel_launch(void* const* d_in, const int* in_sizes, int n_in,
                              void* d_out, int out_size) {
    const float* boxes  = (const float*)d_in[0];   // [8,2048,4] f32
    const float* scores = (const float*)d_in[1];   // [8,2048]   f32
    float* out = (float*)d_out;
    int write_mask = (out_size >= BATCH * MAXDET * 5 + BATCH * MAXDET) ? 1 : 0;

    static int attr_done = 0;
    if (!attr_done) {
        cudaFuncSetAttribute(nms_kernel,
                             cudaFuncAttributeMaxDynamicSharedMemorySize,
                             SMEM_BYTES);
        attr_done = 1;
    }
    nms_kernel<<<BATCH, THREADS, SMEM_BYTES>>>(boxes, scores, out, write_mask);
}

// round 7
// speedup vs baseline: 2.2421x; 1.3119x over previous
#include <cuda_runtime.h>
#include <cuda_bf16.h>

#define BATCH 8
#define NBOX 2048
#define MAXDET 100
#define THREADS 128
#define PER (NBOX / THREADS)   // 16 boxes per thread
#define MIN_SIZE 25.0f
#define SCORE_THR 0.001f
#define DEAD -1.0f
#define CIOU 0.23076923f       // 0.3/1.3 : iou>0.3 <=> inter > CIOU*(A+B)

typedef unsigned long long u64;

// pack (score, idx): larger packed == (higher score, then smaller idx)
__device__ __forceinline__ u64 pack_si(float s, int idx) {
    return ((u64)__float_as_uint(s) << 32) | (unsigned)(~idx);
}

// merge two desc-sorted triples -> desc-sorted top-3 of the union (in a)
__device__ __forceinline__ void merge_top3(u64& a1, u64& a2, u64& a3,
                                           u64 b1, u64 b2, u64 b3) {
    // branchless two-way select network
    bool gA = a1 > b1;
    u64 r1 = gA ? a1 : b1;
    // remaining streams: gA ? ({a2,a3},{b1,b2,b3}) : ({b2,b3},{a1,a2,a3})
    u64 x1 = gA ? a2 : b2, x2 = gA ? a3 : b3;
    u64 y1 = gA ? b1 : a1, y2 = gA ? b2 : a2;
    bool g2 = x1 > y1;
    u64 r2 = g2 ? x1 : y1;
    u64 r3 = g2 ? (x2 > y1 ? x2 : y1) : (x1 > y2 ? x1 : y2);
    a1 = r1; a2 = r2; a3 = r3;
}

__device__ __forceinline__ float ciou_area(float4 b) {
    return CIOU * ((b.z - b.x) * (b.w - b.y));
}
__device__ __forceinline__ float inter_of(float4 a, float4 b) {
    float ix = fminf(a.z, b.z) - fmaxf(a.x, b.x);
    float iy = fminf(a.w, b.w) - fmaxf(a.y, b.y);
    return fmaxf(ix, 0.f) * fmaxf(iy, 0.f);
}

__global__ __launch_bounds__(THREADS, 1)
void nms_kernel(const float* __restrict__ boxes,
                const float* __restrict__ scores,
                float* __restrict__ out,
                int write_mask)
{
    __shared__ float4 sbox[NBOX];            // broadcast table (32 KB)
    __shared__ u64 ws[2][12];                // [parity][warp*3 + {0,1,2}]

    const int img  = blockIdx.x;
    const int tid  = threadIdx.x;
    const int warp = tid >> 5;
    const int lane = tid & 31;

    const float4* bp = (const float4*)(boxes + (size_t)img * NBOX * 4);
    const float*  sp = scores + (size_t)img * NBOX;

    float4 mybox[PER];
    float  mys[PER];
    float  myca[PER];
    #pragma unroll
    for (int p = 0; p < PER; p++) {
        int i = p * THREADS + tid;
        float4 b = bp[i];
        float  s = sp[i];
        float w = b.z - b.x;
        float h = b.w - b.y;
        bool valid = (w >= MIN_SIZE) && (h >= MIN_SIZE) && (s >= SCORE_THR);
        sbox[i]   = b;
        mybox[p]  = b;
        myca[p]   = CIOU * (w * h);
        mys[p]    = valid ? s : DEAD;
    }

    // init output padding: [img,0,0,0,0] rows, mask = 0
    float* outr = out + (size_t)img * MAXDET * 5;
    float* outm = out + (size_t)BATCH * MAXDET * 5 + (size_t)img * MAXDET;
    #pragma unroll
    for (int i = tid; i < MAXDET; i += THREADS) {
        outr[i * 5 + 0] = (float)img;
        outr[i * 5 + 1] = 0.f;
        outr[i * 5 + 2] = 0.f;
        outr[i * 5 + 3] = 0.f;
        outr[i * 5 + 4] = 0.f;
        if (write_mask) outm[i] = 0.f;
    }

    // prologue: thread-local exact top-3 (ascending idx + strict > = min-idx ties)
    float t1 = 0.f, t2 = 0.f, t3 = 0.f; int j1 = 0, j2 = 0, j3 = 0;
    #pragma unroll
    for (int p = 0; p < PER; p++) {
        float s = mys[p]; int idx = p * THREADS + tid;
        bool a = s > t1, b = s > t2, c = s > t3;
        float n1 = a ? s : t1;              int m1 = a ? idx : j1;
        float n2 = a ? t1 : (b ? s : t2);   int m2 = a ? j1 : (b ? idx : j2);
        float n3 = b ? t2 : (c ? s : t3);   int m3 = b ? j2 : (c ? idx : j3);
        t1 = n1; t2 = n2; t3 = n3; j1 = m1; j2 = m2; j3 = m3;
    }
    u64 lp1 = (t1 > 0.f) ? pack_si(t1, j1) : 0ULL;
    u64 lp2 = (t2 > 0.f) ? pack_si(t2, j2) : 0ULL;
    u64 lp3 = (t3 > 0.f) ? pack_si(t3, j3) : 0ULL;

    int k = 0, par = 0;
    while (k < MAXDET) {
        // warp-level exact top-3 butterfly
        u64 m1 = lp1, m2 = lp2, m3 = lp3;
        #pragma unroll
        for (int off = 16; off > 0; off >>= 1) {
            u64 o1 = __shfl_xor_sync(0xffffffffu, m1, off);
            u64 o2 = __shfl_xor_sync(0xffffffffu, m2, off);
            u64 o3 = __shfl_xor_sync(0xffffffffu, m3, off);
            merge_top3(m1, m2, m3, o1, o2, o3);
        }
        if (lane == 0) {
            ws[par][warp * 3 + 0] = m1;
            ws[par][warp * 3 + 1] = m2;
            ws[par][warp * 3 + 2] = m3;
        }
        __syncthreads();

        // merge 4 warp triples -> exact global top-3 (redundant per thread)
        u64 g1 = 0ULL, g2 = 0ULL, g3 = 0ULL;
        #pragma unroll
        for (int j = 0; j < 4; j++)
            merge_top3(g1, g2, g3, ws[par][3 * j], ws[par][3 * j + 1], ws[par][3 * j + 2]);
        par ^= 1;

        if (g1 == 0ULL) break;                     // nothing live (uniform)

        int c1 = (int)~(unsigned)(g1 & 0xffffffffu);
        float4 cb1 = sbox[c1];
        float ca1 = ciou_area(cb1);

        bool has2 = (g2 != 0ULL), has3 = (g3 != 0ULL);
        float4 cb2 = has2 ? sbox[(int)~(unsigned)(g2 & 0xffffffffu)] : cb1;
        float4 cb3 = has3 ? sbox[(int)~(unsigned)(g3 & 0xffffffffu)] : cb1;
        float ca2 = ciou_area(cb2);
        float ca3 = ciou_area(cb3);

        // verification: which speculative candidates are true greedy picks?
        bool ok12 = !(inter_of(cb1, cb2) > ca1 + ca2);
        bool ok13 = !(inter_of(cb1, cb3) > ca1 + ca3);
        bool ok23 = !(inter_of(cb2, cb3) > ca2 + ca3);
        bool sel2 = has2 && ok12;
        bool sel3 = has3 && ok13 && (!sel2 || ok23);

        // only selected boxes suppress; alias rejected ones to cb1 (idempotent)
        if (!sel2) { cb2 = cb1; ca2 = ca1; }
        if (!sel3) { cb3 = cb1; ca3 = ca1; }

        if (tid == 0) {
            outr[k * 5 + 1] = cb1.x;
            outr[k * 5 + 2] = cb1.y;
            outr[k * 5 + 3] = cb1.z;
            outr[k * 5 + 4] = cb1.w;
            if (write_mask) outm[k] = 1.f;
            int kk = k + 1;
            if (sel2 && kk < MAXDET) {
                outr[kk * 5 + 1] = cb2.x;
                outr[kk * 5 + 2] = cb2.y;
                outr[kk * 5 + 3] = cb2.z;
                outr[kk * 5 + 4] = cb2.w;
                if (write_mask) outm[kk] = 1.f;
                kk++;
            }
            if (sel3 && kk < MAXDET) {
                outr[kk * 5 + 1] = cb3.x;
                outr[kk * 5 + 2] = cb3.y;
                outr[kk * 5 + 3] = cb3.z;
                outr[kk * 5 + 4] = cb3.w;
                if (write_mask) outm[kk] = 1.f;
            }
        }

        // fused: triple suppression + next thread-local top-3
        t1 = 0.f; t2 = 0.f; t3 = 0.f; j1 = 0; j2 = 0; j3 = 0;
        #pragma unroll
        for (int p = 0; p < PER; p++) {
            float4 b = mybox[p];
            float in1 = inter_of(cb1, b);
            float in2 = inter_of(cb2, b);
            float in3 = inter_of(cb3, b);
            float cab = myca[p];
            bool dead = (in1 > ca1 + cab) || (in2 > ca2 + cab) || (in3 > ca3 + cab);
            float s = dead ? DEAD : mys[p];
            mys[p] = s;
            int idx = p * THREADS + tid;
            bool a = s > t1, bb = s > t2, c = s > t3;
            float n1 = a ? s : t1;               int m1i = a ? idx : j1;
            float n2 = a ? t1 : (bb ? s : t2);   int m2i = a ? j1 : (bb ? idx : j2);
            float n3 = bb ? t2 : (c ? s : t3);   int m3i = bb ? j2 : (c ? idx : j3);
            t1 = n1; t2 = n2; t3 = n3; j1 = m1i; j2 = m2i; j3 = m3i;
        }
        lp1 = (t1 > 0.f) ? pack_si(t1, j1) : 0ULL;
        lp2 = (t2 > 0.f) ? pack_si(t2, j2) : 0ULL;
        lp3 = (t3 > 0.f) ? pack_si(t3, j3) : 0ULL;

        k += 1 + (sel2 ? 1 : 0) + (sel3 ? 1 : 0);
    }
}

extern "C" void kernel_launch(void* const* d_in, const int* in_sizes, int n_in,
                              void* d_out, int out_size) {
    const float* boxes  = (const float*)d_in[0];   // [8,2048,4] f32
    const float* scores = (const float*)d_in[1];   // [8,2048]   f32
    float* out = (float*)d_out;
    int write_mask = (out_size >= BATCH * MAXDET * 5 + BATCH * MAXDET) ? 1 : 0;
    nms_kernel<<<BATCH, THREADS>>>(boxes, scores, out, write_mask);
}